// round 16
// baseline (speedup 1.0000x reference)
#include <cuda_runtime.h>
#include <cooperative_groups.h>

namespace cg = cooperative_groups;

// FPS, torch_geometric semantics. 16 clouds x 16384 -> 4096 samples/cloud.
// TWO clouds per 4-CTA cluster (8 clusters, 32 CTAs): both clouds share ONE
// cluster.sync per iteration, amortizing the serial exchange tail. Protocol
// per cloud is byte-identical to R15 (proven): warp redux -> skeys ->
// __syncthreads -> CTA redux scan -> unique owner publishes one record to all
// 4 CTAs -> shared cluster.sync -> redux combine.
// Bit-exact arithmetic (validated R6+): d=(dx*dx+dy*dy)+dz*dz, RN, no FMA
// contraction, sub = add of negated. Keys: high=dist bits, low=~idx (first-
// occurrence argmax). redux two-step validated R12+.
// Output: float32 values of global indices.

#define N_CLOUDS 16
#define PTS      16384
#define M_SAMP   4096
#define THREADS  512
#define CL       4
#define QTR      4096
#define PAIRS    4       // 8 points per thread per cloud = 4 f32x2 pairs
#define NW       16      // warps per CTA

__device__ __forceinline__ unsigned long long pack2(float lo, float hi) {
    unsigned long long r;
    asm("mov.b64 %0, {%1, %2};" : "=l"(r) : "f"(lo), "f"(hi));
    return r;
}
__device__ __forceinline__ void unpack2(unsigned long long v, float& lo, float& hi) {
    asm("mov.b64 {%0, %1}, %2;" : "=f"(lo), "=f"(hi) : "l"(v));
}
// Packed IEEE RN f32x2 ops (sm_100+): bit-identical to scalar FADD/FMUL.
__device__ __forceinline__ unsigned long long add2(unsigned long long a, unsigned long long b) {
    unsigned long long r;
    asm("add.rn.f32x2 %0, %1, %2;" : "=l"(r) : "l"(a), "l"(b));
    return r;
}
__device__ __forceinline__ unsigned long long mul2(unsigned long long a, unsigned long long b) {
    unsigned long long r;
    asm("mul.rn.f32x2 %0, %1, %2;" : "=l"(r) : "l"(a), "l"(b));
    return r;
}
__device__ __forceinline__ unsigned int redux_umax(unsigned int v) {
    unsigned int r;
    asm("redux.sync.max.u32 %0, %1, 0xffffffff;" : "=r"(r) : "r"(v));
    return r;
}

struct __align__(8) Slot { unsigned long long key; unsigned long long xy; float z_; };

// Bit-exact min-dist update + thread-local argmax for one cloud.
__device__ __forceinline__ void update_cloud(
    const unsigned long long (&CX)[PAIRS], const unsigned long long (&CY)[PAIRS],
    const unsigned long long (&CZ)[PAIRS], float (&d)[2 * PAIRS],
    float sx, float sy, float sz, float& best, int& jj)
{
    const unsigned long long nx2 = pack2(-sx, -sx);
    const unsigned long long ny2 = pack2(-sy, -sy);
    const unsigned long long nz2 = pack2(-sz, -sz);
    best = 0.0f; jj = 0;
#pragma unroll
    for (int pr = 0; pr < PAIRS; ++pr) {
        unsigned long long dx = add2(CX[pr], nx2);           // exact sub
        unsigned long long dy = add2(CY[pr], ny2);
        unsigned long long dz = add2(CZ[pr], nz2);
        unsigned long long s  = add2(add2(mul2(dx, dx), mul2(dy, dy)), mul2(dz, dz));
        float lo, hi;
        unpack2(s, lo, hi);
        {
            float nd = fminf(d[2 * pr], lo);
            d[2 * pr] = nd;
            bool c = nd > best; best = c ? nd : best; jj = c ? 2 * pr : jj;
        }
        {
            float nd = fminf(d[2 * pr + 1], hi);
            d[2 * pr + 1] = nd;
            bool c = nd > best; best = c ? nd : best; jj = c ? 2 * pr + 1 : jj;
        }
    }
}

// Owner coord extraction (compile-time indexed, predicated).
__device__ __forceinline__ void extract_coords(
    const unsigned long long (&CX)[PAIRS], const unsigned long long (&CY)[PAIRS],
    const unsigned long long (&CZ)[PAIRS], int jj, float& wx, float& wy, float& wz)
{
    const int prw = jj >> 1;
    const int hw  = jj & 1;
    wx = 0.f; wy = 0.f; wz = 0.f;
#pragma unroll
    for (int pr = 0; pr < PAIRS; ++pr) {
        if (pr == prw) {
            float l0, h0, l1, h1, l2, h2;
            unpack2(CX[pr], l0, h0);
            unpack2(CY[pr], l1, h1);
            unpack2(CZ[pr], l2, h2);
            wx = hw ? h0 : l0;
            wy = hw ? h1 : l1;
            wz = hw ? h2 : l2;
        }
    }
}

__global__ __launch_bounds__(THREADS, 1) __cluster_dims__(CL, 1, 1)
void fps_kernel(const float* __restrict__ pos, float* __restrict__ out)
{
    __shared__ unsigned long long skA[2][NW], skB[2][NW];
    __shared__ Slot slotsA[2][CL], slotsB[2][CL];

    cg::cluster_group cluster = cg::this_cluster();
    const unsigned rank = cluster.block_rank();          // 0..3
    const int cid  = blockIdx.x >> 2;                    // cluster id = cloud pair
    const int cA   = 2 * cid, cB = 2 * cid + 1;
    const int base = (int)rank * QTR;

    const int t    = threadIdx.x;
    const int lane = t & 31;
    const int wid  = t >> 5;
    const float* pA = pos + (size_t)cA * PTS * 3;
    const float* pB = pos + (size_t)cB * PTS * 3;

    unsigned long long AX[PAIRS], AY[PAIRS], AZ[PAIRS];
    unsigned long long BX[PAIRS], BY[PAIRS], BZ[PAIRS];
    float dA[2 * PAIRS], dB[2 * PAIRS];
    const float INF = __int_as_float(0x7f800000);

#pragma unroll
    for (int pr = 0; pr < PAIRS; ++pr) {
        int g0 = base + t + ((2 * pr)     << 9);
        int g1 = base + t + ((2 * pr + 1) << 9);
        AX[pr] = pack2(pA[3 * g0 + 0], pA[3 * g1 + 0]);
        AY[pr] = pack2(pA[3 * g0 + 1], pA[3 * g1 + 1]);
        AZ[pr] = pack2(pA[3 * g0 + 2], pA[3 * g1 + 2]);
        BX[pr] = pack2(pB[3 * g0 + 0], pB[3 * g1 + 0]);
        BY[pr] = pack2(pB[3 * g0 + 1], pB[3 * g1 + 1]);
        BZ[pr] = pack2(pB[3 * g0 + 2], pB[3 * g1 + 2]);
        dA[2 * pr] = INF; dA[2 * pr + 1] = INF;
        dB[2 * pr] = INF; dB[2 * pr + 1] = INF;
    }

    float sxA = pA[0], syA = pA[1], szA = pA[2];
    float sxB = pB[0], syB = pB[1], szB = pB[2];
    if (t == 0 && rank == 0) {
        out[cA * M_SAMP] = (float)(cA * PTS);
        out[cB * M_SAMP] = (float)(cB * PTS);
    }

    cluster.sync();   // cluster alive before first DSMEM publish

    for (int i = 1; i < M_SAMP; ++i) {
        // ---- updates (bulk issue work; A and B chains independent) ----
        float bestA, bestB; int jjA, jjB;
        update_cloud(AX, AY, AZ, dA, sxA, syA, szA, bestA, jjA);
        update_cloud(BX, BY, BZ, dB, sxB, syB, szB, bestB, jjB);

        const unsigned int giA  = (unsigned int)(base + t) + ((unsigned int)jjA << 9);
        const unsigned int bitA = __float_as_uint(bestA);
        const unsigned int invA = 0xFFFFFFFFu - giA;
        const unsigned int giB  = (unsigned int)(base + t) + ((unsigned int)jjB << 9);
        const unsigned int bitB = __float_as_uint(bestB);
        const unsigned int invB = 0xFFFFFFFFu - giB;

        // Warp argmax, both clouds (independent redux chains overlap).
        const unsigned int wbA = redux_umax(bitA);
        const unsigned int wbB = redux_umax(bitB);
        const unsigned int wiA = redux_umax(bitA == wbA ? invA : 0u);
        const unsigned int wiB = redux_umax(bitB == wbB ? invB : 0u);

        const int par = i & 1;
        if (lane == 0) {
            skA[par][wid] = ((unsigned long long)wbA << 32) | wiA;
            skB[par][wid] = ((unsigned long long)wbB << 32) | wiB;
        }
        __syncthreads();                                   // the one CTA barrier

        // CTA scans via redux.
        unsigned long long kwA = (lane < NW) ? skA[par][lane] : 0ull;
        unsigned long long kwB = (lane < NW) ? skB[par][lane] : 0ull;
        const unsigned int cbA = redux_umax((unsigned int)(kwA >> 32));
        const unsigned int cbB = redux_umax((unsigned int)(kwB >> 32));
        const unsigned int ciA = redux_umax((unsigned int)(kwA >> 32) == cbA ? (unsigned int)kwA : 0u);
        const unsigned int ciB = redux_umax((unsigned int)(kwB >> 32) == cbB ? (unsigned int)kwB : 0u);

        // Unique owners publish one record each to all 4 CTAs.
        if (bitA == cbA && invA == ciA) {
            float wx, wy, wz;
            extract_coords(AX, AY, AZ, jjA, wx, wy, wz);
            const unsigned long long key64 =
                ((unsigned long long)cbA << 32) | (unsigned long long)ciA;
            const unsigned long long xy = pack2(wx, wy);
            slotsA[par][rank].key = key64;
            slotsA[par][rank].xy  = xy;
            slotsA[par][rank].z_  = wz;
#pragma unroll
            for (unsigned pr_ = 1; pr_ < CL; ++pr_) {
                const unsigned peer = (rank + pr_) & (CL - 1);
                Slot* rs = cluster.map_shared_rank(&slotsA[par][rank], peer);
                rs->key = key64; rs->xy = xy; rs->z_ = wz;
            }
        }
        if (bitB == cbB && invB == ciB) {
            float wx, wy, wz;
            extract_coords(BX, BY, BZ, jjB, wx, wy, wz);
            const unsigned long long key64 =
                ((unsigned long long)cbB << 32) | (unsigned long long)ciB;
            const unsigned long long xy = pack2(wx, wy);
            slotsB[par][rank].key = key64;
            slotsB[par][rank].xy  = xy;
            slotsB[par][rank].z_  = wz;
#pragma unroll
            for (unsigned pr_ = 1; pr_ < CL; ++pr_) {
                const unsigned peer = (rank + pr_) & (CL - 1);
                Slot* rs = cluster.map_shared_rank(&slotsB[par][rank], peer);
                rs->key = key64; rs->xy = xy; rs->z_ = wz;
            }
        }

        // ONE shared cluster barrier for both clouds.
        cluster.sync();

        // Combines via redux.
        {
            const unsigned long long ks = (lane < CL) ? slotsA[par][lane].key : 0ull;
            const unsigned int grb = redux_umax((unsigned int)(ks >> 32));
            const unsigned int gri = redux_umax((unsigned int)(ks >> 32) == grb ? (unsigned int)ks : 0u);
            const unsigned int gw = 0xFFFFFFFFu - gri;
            const unsigned int ws = gw >> 12;
            unpack2(slotsA[par][ws].xy, sxA, syA);
            szA = slotsA[par][ws].z_;
            if (t == 0 && rank == 0)
                out[cA * M_SAMP + i] = (float)(cA * PTS + (int)gw);
        }
        {
            const unsigned long long ks = (lane < CL) ? slotsB[par][lane].key : 0ull;
            const unsigned int grb = redux_umax((unsigned int)(ks >> 32));
            const unsigned int gri = redux_umax((unsigned int)(ks >> 32) == grb ? (unsigned int)ks : 0u);
            const unsigned int gw = 0xFFFFFFFFu - gri;
            const unsigned int ws = gw >> 12;
            unpack2(slotsB[par][ws].xy, sxB, syB);
            szB = slotsB[par][ws].z_;
            if (t == 0 && rank == 0)
                out[cB * M_SAMP + i] = (float)(cB * PTS + (int)gw);
        }
    }
}

extern "C" void kernel_launch(void* const* d_in, const int* in_sizes, int n_in,
                              void* d_out, int out_size)
{
    // Resolve pos BY SIZE (786432 floats), robust to input ordering.
    const float* pos = nullptr;
    for (int i = 0; i < n_in; ++i) {
        if (in_sizes[i] == N_CLOUDS * PTS * 3) { pos = (const float*)d_in[i]; break; }
    }
    if (!pos) pos = (const float*)d_in[0];

    float* out = (float*)d_out;   // [N_CLOUDS*M_SAMP] float32 index values

    fps_kernel<<<(N_CLOUDS / 2) * CL, THREADS>>>(pos, out);
}